// round 1
// baseline (speedup 1.0000x reference)
#include <cuda_runtime.h>
#include <math.h>

#define BB 2048
#define SS 200
#define DD 128
#define HH 64
#define MASK_SCALE 1e10f
#define NT 256

// Precomputed folded weights and per-batch bias vector
__device__ float g_Wa[DD * HH];          // W1 + W2   [128,64]
__device__ float g_Wb[DD * HH];          // W3 - W2   [128,64]
__device__ float g_c[BB * HH];           // tgt @ Wb + W_bias  [2048,64]

__global__ void fold_w_kernel(const float* __restrict__ W) {
    int idx = blockIdx.x * blockDim.x + threadIdx.x;
    if (idx < DD * HH) {
        int k = idx / HH, j = idx % HH;
        float w1 = W[k * HH + j];
        float w2 = W[(DD + k) * HH + j];
        float w3 = W[(2 * DD + k) * HH + j];
        g_Wa[idx] = w1 + w2;
        g_Wb[idx] = w3 - w2;
    }
}

__global__ void cvec_kernel(const float* __restrict__ target,
                            const float* __restrict__ W_bias) {
    __shared__ float tgt[DD];
    int b = blockIdx.x;
    for (int i = threadIdx.x; i < DD; i += blockDim.x)
        tgt[i] = target[(size_t)b * DD + i];
    __syncthreads();
    int h = threadIdx.x;
    if (h < HH) {
        float acc = 0.f;
#pragma unroll 8
        for (int d = 0; d < DD; d++)
            acc = fmaf(tgt[d], g_Wb[d * HH + h], acc);
        g_c[b * HH + h] = acc + W_bias[h];
    }
}

// Main kernel: one block per batch row. Single pass over his.
__global__ __launch_bounds__(NT, 1)
void ta_main_kernel(const float* __restrict__ his,
                    const float* __restrict__ mask,
                    const float* __restrict__ O,
                    const float* __restrict__ O_bias,
                    float* __restrict__ out) {
    extern __shared__ float sm[];
    float* his_s  = sm;                       // SS*DD = 25600
    float* Wa_s   = his_s + SS * DD;          // DD*HH = 8192 (reused as pool scratch)
    float* alpha  = Wa_s + DD * HH;           // SS
    float* mask_s = alpha + SS;               // SS
    float* c_s    = mask_s + SS;              // HH
    float* O_s    = c_s + HH;                 // HH
    float* red    = O_s + HH;                 // 8
    float* red2   = red + 8;                  // 8

    const int b = blockIdx.x;
    const int tid = threadIdx.x;
    const int wid = tid >> 5;
    const int lane = tid & 31;

    // ---- Phase 0: cooperative loads ----
    {
        const float4* hg = (const float4*)(his + (size_t)b * SS * DD);
        float4* hs4 = (float4*)his_s;
        const int n4 = SS * DD / 4;      // 6400
#pragma unroll 4
        for (int i = tid; i < n4; i += NT) hs4[i] = hg[i];

        const float4* wg = (const float4*)g_Wa;
        float4* ws4 = (float4*)Wa_s;
        for (int i = tid; i < DD * HH / 4; i += NT) ws4[i] = wg[i];

        if (tid < SS) mask_s[tid] = mask[(size_t)b * SS + tid];
        if (tid < HH) { c_s[tid] = g_c[b * HH + tid]; O_s[tid] = O[tid]; }
    }
    const float ob = O_bias[0];
    __syncthreads();

    // ---- Phase 1: GEMM [200x128]@[128x64] + relu + dot(O) -> alpha[s] ----
    // Each warp processes 4 s-rows per group; lane owns columns (2*lane, 2*lane+1).
    for (int g = wid; g < SS / 4; g += NT / 32) {
        const int s0 = g * 4;
        float acc00 = 0.f, acc01 = 0.f, acc10 = 0.f, acc11 = 0.f;
        float acc20 = 0.f, acc21 = 0.f, acc30 = 0.f, acc31 = 0.f;
        const int col = lane << 1;
#pragma unroll 2
        for (int k = 0; k < DD; k += 4) {
            float4 a0 = *(const float4*)(his_s + (s0 + 0) * DD + k);
            float4 a1 = *(const float4*)(his_s + (s0 + 1) * DD + k);
            float4 a2 = *(const float4*)(his_s + (s0 + 2) * DD + k);
            float4 a3 = *(const float4*)(his_s + (s0 + 3) * DD + k);
            float xr[4][4];
            xr[0][0]=a0.x; xr[0][1]=a0.y; xr[0][2]=a0.z; xr[0][3]=a0.w;
            xr[1][0]=a1.x; xr[1][1]=a1.y; xr[1][2]=a1.z; xr[1][3]=a1.w;
            xr[2][0]=a2.x; xr[2][1]=a2.y; xr[2][2]=a2.z; xr[2][3]=a2.w;
            xr[3][0]=a3.x; xr[3][1]=a3.y; xr[3][2]=a3.z; xr[3][3]=a3.w;
#pragma unroll
            for (int kk = 0; kk < 4; kk++) {
                float2 w = *(const float2*)(Wa_s + (k + kk) * HH + col);
                acc00 = fmaf(xr[0][kk], w.x, acc00);
                acc01 = fmaf(xr[0][kk], w.y, acc01);
                acc10 = fmaf(xr[1][kk], w.x, acc10);
                acc11 = fmaf(xr[1][kk], w.y, acc11);
                acc20 = fmaf(xr[2][kk], w.x, acc20);
                acc21 = fmaf(xr[2][kk], w.y, acc21);
                acc30 = fmaf(xr[3][kk], w.x, acc30);
                acc31 = fmaf(xr[3][kk], w.y, acc31);
            }
        }
        const float c0 = c_s[col], c1 = c_s[col + 1];
        const float o0 = O_s[col], o1 = O_s[col + 1];
        float v0 = fmaxf(acc00 + c0, 0.f) * o0 + fmaxf(acc01 + c1, 0.f) * o1;
        float v1 = fmaxf(acc10 + c0, 0.f) * o0 + fmaxf(acc11 + c1, 0.f) * o1;
        float v2 = fmaxf(acc20 + c0, 0.f) * o0 + fmaxf(acc21 + c1, 0.f) * o1;
        float v3 = fmaxf(acc30 + c0, 0.f) * o0 + fmaxf(acc31 + c1, 0.f) * o1;
#pragma unroll
        for (int off = 16; off > 0; off >>= 1) {
            v0 += __shfl_xor_sync(0xffffffffu, v0, off);
            v1 += __shfl_xor_sync(0xffffffffu, v1, off);
            v2 += __shfl_xor_sync(0xffffffffu, v2, off);
            v3 += __shfl_xor_sync(0xffffffffu, v3, off);
        }
        if (lane == 0) {
            alpha[s0 + 0] = v0 + ob - mask_s[s0 + 0] * MASK_SCALE;
            alpha[s0 + 1] = v1 + ob - mask_s[s0 + 1] * MASK_SCALE;
            alpha[s0 + 2] = v2 + ob - mask_s[s0 + 2] * MASK_SCALE;
            alpha[s0 + 3] = v3 + ob - mask_s[s0 + 3] * MASK_SCALE;
        }
    }
    __syncthreads();

    // ---- Phase 2: softmax over alpha[0..199] ----
    {
        float v = (tid < SS) ? alpha[tid] : -INFINITY;
        float m = v;
#pragma unroll
        for (int off = 16; off > 0; off >>= 1)
            m = fmaxf(m, __shfl_xor_sync(0xffffffffu, m, off));
        if (lane == 0) red[wid] = m;
        __syncthreads();
        m = red[0];
#pragma unroll
        for (int w = 1; w < NT / 32; w++) m = fmaxf(m, red[w]);

        float e = (tid < SS) ? __expf(v - m) : 0.f;
        float s = e;
#pragma unroll
        for (int off = 16; off > 0; off >>= 1)
            s += __shfl_xor_sync(0xffffffffu, s, off);
        if (lane == 0) red2[wid] = s;
        __syncthreads();
        float tot = 0.f;
#pragma unroll
        for (int w = 0; w < NT / 32; w++) tot += red2[w];

        if (tid < SS) alpha[tid] = e / tot;   // attn weights
    }
    __syncthreads();

    // ---- Phase 3: pooling out[b,d] = sum_s attn[s]*his[s,d] ----
    {
        const int d = tid & (DD - 1);
        const int half = tid >> 7;               // 0 or 1
        const int sbeg = half * (SS / 2);
        const int send = sbeg + (SS / 2);
        float acc = 0.f;
#pragma unroll 4
        for (int s = sbeg; s < send; s++)
            acc = fmaf(alpha[s], his_s[s * DD + d], acc);
        Wa_s[half * DD + d] = acc;               // reuse Wa smem as scratch
        __syncthreads();
        if (tid < DD)
            out[(size_t)b * DD + tid] = Wa_s[tid] + Wa_s[DD + tid];
    }
}

static const size_t SMEM_BYTES =
    (size_t)(SS * DD + DD * HH + SS + SS + HH + HH + 16) * sizeof(float);

extern "C" void kernel_launch(void* const* d_in, const int* in_sizes, int n_in,
                              void* d_out, int out_size) {
    const float* his    = (const float*)d_in[0];
    const float* target = (const float*)d_in[1];
    const float* mask   = (const float*)d_in[2];
    const float* W      = (const float*)d_in[3];
    const float* W_bias = (const float*)d_in[4];
    const float* O      = (const float*)d_in[5];
    const float* O_bias = (const float*)d_in[6];
    float* out = (float*)d_out;

    cudaFuncSetAttribute(ta_main_kernel,
                         cudaFuncAttributeMaxDynamicSharedMemorySize,
                         (int)SMEM_BYTES);

    fold_w_kernel<<<(DD * HH + 255) / 256, 256>>>(W);
    cvec_kernel<<<BB, 128>>>(target, W_bias);
    ta_main_kernel<<<BB, NT, SMEM_BYTES>>>(his, mask, O, O_bias, out);
}

// round 2
// speedup vs baseline: 1.4342x; 1.4342x over previous
#include <cuda_runtime.h>
#include <math.h>

#define BB 2048
#define SS 200
#define DD 128
#define HH 64
#define KK2 (DD / 2)            // 64 packed-k pairs
#define MASK_SCALE 1e10f
#define NT 256
#define NW (NT / 32)
#define ROWS_PER_WARP (SS / NW) // 25
#define RTILE 5                 // rows per register tile (5 tiles/warp)

typedef unsigned long long u64;

// Folded weights (packed over k-pairs) and per-batch bias vector
__device__ float2 g_WaP[KK2 * HH];   // [k2][c] = (Wa[2k2][c], Wa[2k2+1][c]),  Wa = W1+W2
__device__ float  g_Wb[DD * HH];     // W3 - W2
__device__ float  g_c[BB * HH];      // tgt @ Wb + W_bias

__device__ __forceinline__ void fma2(u64& d, u64 a, u64 b) {
    asm("fma.rn.f32x2 %0, %1, %2, %0;" : "+l"(d) : "l"(a), "l"(b));
}
__device__ __forceinline__ float lo32(u64 v) { return __uint_as_float((unsigned)(v & 0xffffffffull)); }
__device__ __forceinline__ float hi32(u64 v) { return __uint_as_float((unsigned)(v >> 32)); }

__device__ __forceinline__ void cpa16(void* s, const void* g) {
    unsigned sa = (unsigned)__cvta_generic_to_shared(s);
    asm volatile("cp.async.cg.shared.global [%0], [%1], 16;" :: "r"(sa), "l"(g));
}
#define CP_COMMIT() asm volatile("cp.async.commit_group;")
#define CP_WAIT(n)  asm volatile("cp.async.wait_group %0;" :: "n"(n))

__global__ void fold_w_kernel(const float* __restrict__ W) {
    int idx = blockIdx.x * blockDim.x + threadIdx.x;   // over DD*HH
    if (idx < DD * HH) {
        int k = idx / HH, c = idx % HH;
        float w1 = W[k * HH + c];
        float w2 = W[(DD + k) * HH + c];
        float w3 = W[(2 * DD + k) * HH + c];
        float wa = w1 + w2;
        g_Wb[idx] = w3 - w2;
        // packed layout: g_WaP[(k/2)*HH + c].x|y for even|odd k
        if (k & 1) g_WaP[(k >> 1) * HH + c].y = wa;
        else       g_WaP[(k >> 1) * HH + c].x = wa;
    }
}

__global__ void cvec_kernel(const float* __restrict__ target,
                            const float* __restrict__ W_bias) {
    __shared__ float tgt[DD];
    int b = blockIdx.x;
    for (int i = threadIdx.x; i < DD; i += blockDim.x)
        tgt[i] = target[(size_t)b * DD + i];
    __syncthreads();
    int h = threadIdx.x;
    if (h < HH) {
        float acc = 0.f;
#pragma unroll 8
        for (int d = 0; d < DD; d++)
            acc = fmaf(tgt[d], g_Wb[d * HH + h], acc);
        g_c[b * HH + h] = acc + W_bias[h];
    }
}

__global__ __launch_bounds__(NT, 1)
void ta_main_kernel(const float* __restrict__ his,
                    const float* __restrict__ mask,
                    const float* __restrict__ O,
                    const float* __restrict__ O_bias,
                    float* __restrict__ out) {
    extern __shared__ float sm[];
    float* his_s  = sm;                        // SS*DD = 25600 f
    float* w_s    = his_s + SS * DD;           // KK2*HH*2 = 8192 f (reused as pool scratch)
    float* alpha  = w_s + KK2 * HH * 2;        // SS
    float* mask_s = alpha + SS;                // SS
    float* c_s    = mask_s + SS;               // HH
    float* O_s    = c_s + HH;                  // HH
    float* red    = O_s + HH;                  // 8
    float* red2   = red + 8;                   // 8

    const int b = blockIdx.x;
    const int tid = threadIdx.x;
    const int wid = tid >> 5;
    const int lane = tid & 31;

    // ---- Phase 0: async loads ----
    // Group 0: folded weight (shared by all warps)
    {
        const char* wg = (const char*)g_WaP;
        char* ws = (char*)w_s;
        for (int i = tid; i < (KK2 * HH * 8) / 16; i += NT)   // 2048 ops
            cpa16(ws + i * 16, wg + i * 16);
    }
    CP_COMMIT();
    // Group 1: this warp's 25 rows of his
    {
        const char* hg = (const char*)(his + (size_t)b * SS * DD + wid * ROWS_PER_WARP * DD);
        char* hs = (char*)(his_s + wid * ROWS_PER_WARP * DD);
        const int nops = ROWS_PER_WARP * DD * 4 / 16;         // 800
        for (int i = lane; i < nops; i += 32)
            cpa16(hs + i * 16, hg + i * 16);
    }
    CP_COMMIT();
    // Small direct loads
    if (tid < SS) mask_s[tid] = mask[(size_t)b * SS + tid];
    if (tid < HH) { c_s[tid] = g_c[b * HH + tid]; O_s[tid] = O[tid]; }
    const float ob = O_bias[0];

    CP_WAIT(1);            // weight group done (per-thread)
    __syncthreads();       // weight + small loads visible block-wide
    CP_WAIT(0);            // this warp's his rows done
    __syncwarp();

    // ---- Phase 1: GEMM via packed f32x2 FMA -> alpha[s] ----
    const u64* his_u = (const u64*)his_s;
    const u64* w_u   = (const u64*)w_s;
    const int c0 = lane, c1 = lane + 32;
    const float cb0 = c_s[c0], cb1 = c_s[c1];
    const float oo0 = O_s[c0], oo1 = O_s[c1];

    for (int grp = 0; grp < ROWS_PER_WARP / RTILE; grp++) {
        const int s0 = wid * ROWS_PER_WARP + grp * RTILE;
        u64 acc[RTILE][2];
#pragma unroll
        for (int r = 0; r < RTILE; r++) { acc[r][0] = 0ull; acc[r][1] = 0ull; }

#pragma unroll 4
        for (int k2 = 0; k2 < KK2; k2 += 2) {
            u64 w00 = w_u[(size_t)k2 * HH + c0];
            u64 w01 = w_u[(size_t)k2 * HH + c1];
            u64 w10 = w_u[(size_t)(k2 + 1) * HH + c0];
            u64 w11 = w_u[(size_t)(k2 + 1) * HH + c1];
#pragma unroll
            for (int r = 0; r < RTILE; r++) {
                ulonglong2 x = *(const ulonglong2*)(his_u + (size_t)(s0 + r) * KK2 + k2);
                fma2(acc[r][0], x.x, w00);
                fma2(acc[r][1], x.x, w01);
                fma2(acc[r][0], x.y, w10);
                fma2(acc[r][1], x.y, w11);
            }
        }

        float v[RTILE];
#pragma unroll
        for (int r = 0; r < RTILE; r++) {
            float h0 = lo32(acc[r][0]) + hi32(acc[r][0]) + cb0;
            float h1 = lo32(acc[r][1]) + hi32(acc[r][1]) + cb1;
            v[r] = fmaxf(h0, 0.f) * oo0 + fmaxf(h1, 0.f) * oo1;
        }
#pragma unroll
        for (int off = 16; off > 0; off >>= 1) {
#pragma unroll
            for (int r = 0; r < RTILE; r++)
                v[r] += __shfl_xor_sync(0xffffffffu, v[r], off);
        }
        if (lane < RTILE)
            alpha[s0 + lane] = v[lane] + ob - mask_s[s0 + lane] * MASK_SCALE;
        // lane<RTILE holds reduced v[lane]? No: every lane holds all v[r].
        // (shfl_xor full-butterfly leaves the total in every lane, so the
        //  write above is correct: lane r writes v[r].)
    }
    __syncthreads();

    // ---- Phase 2: softmax over alpha[0..SS) ----
    {
        float vv = (tid < SS) ? alpha[tid] : -INFINITY;
        float m = vv;
#pragma unroll
        for (int off = 16; off > 0; off >>= 1)
            m = fmaxf(m, __shfl_xor_sync(0xffffffffu, m, off));
        if (lane == 0) red[wid] = m;
        __syncthreads();
        m = red[0];
#pragma unroll
        for (int w = 1; w < NW; w++) m = fmaxf(m, red[w]);

        float e = (tid < SS) ? __expf(vv - m) : 0.f;
        float s = e;
#pragma unroll
        for (int off = 16; off > 0; off >>= 1)
            s += __shfl_xor_sync(0xffffffffu, s, off);
        if (lane == 0) red2[wid] = s;
        __syncthreads();
        float tot = 0.f;
#pragma unroll
        for (int w = 0; w < NW; w++) tot += red2[w];

        if (tid < SS) alpha[tid] = e / tot;
    }
    __syncthreads();

    // ---- Phase 3: pooling out[b,d] = sum_s attn[s]*his[s,d] ----
    {
        const int d = tid & (DD - 1);
        const int half = tid >> 7;
        const int sbeg = half * (SS / 2);
        const int send = sbeg + (SS / 2);
        float acc = 0.f;
#pragma unroll 4
        for (int s = sbeg; s < send; s++)
            acc = fmaf(alpha[s], his_s[s * DD + d], acc);
        w_s[half * DD + d] = acc;                 // reuse weight smem as scratch
        __syncthreads();
        if (tid < DD)
            out[(size_t)b * DD + tid] = w_s[tid] + w_s[DD + tid];
    }
}

static const size_t SMEM_BYTES =
    (size_t)(SS * DD + KK2 * HH * 2 + SS + SS + HH + HH + 16) * sizeof(float);

extern "C" void kernel_launch(void* const* d_in, const int* in_sizes, int n_in,
                              void* d_out, int out_size) {
    const float* his    = (const float*)d_in[0];
    const float* target = (const float*)d_in[1];
    const float* mask   = (const float*)d_in[2];
    const float* W      = (const float*)d_in[3];
    const float* W_bias = (const float*)d_in[4];
    const float* O      = (const float*)d_in[5];
    const float* O_bias = (const float*)d_in[6];
    float* out = (float*)d_out;

    cudaFuncSetAttribute(ta_main_kernel,
                         cudaFuncAttributeMaxDynamicSharedMemorySize,
                         (int)SMEM_BYTES);

    fold_w_kernel<<<(DD * HH + 255) / 256, 256>>>(W);
    cvec_kernel<<<BB, 128>>>(target, W_bias);
    ta_main_kernel<<<BB, NT, SMEM_BYTES>>>(his, mask, O, O_bias, out);
}

// round 4
// speedup vs baseline: 2.1268x; 1.4829x over previous
#include <cuda_runtime.h>
#include <cuda_bf16.h>
#include <math.h>
#include <stdint.h>

#define BB 2048
#define SS 200
#define DD 128
#define HH 64
#define MASK_SCALE 1e10f
#define NT 256
#define NW (NT / 32)
#define ROWS_PER_WARP (SS / NW)      // 25
#define NSTRIP 13                    // ceil(200/16), rows 200..207 zero-padded

#define ASTRIDE 272                  // bytes per A row (136 bf16) = 17*16
#define BSTRIDE 144                  // bytes per B row (72 bf16)  = 9*16

// ---- smem byte layout ----
#define A_HI_OFF   0                         // 208*272 = 56576
#define A_LO_OFF   56576                     // 56576
#define B_HI_OFF   113152                    // 128*144 = 18432
#define B_LO_OFF   131584                    // 18432
#define SM_ALPHA   150016                    // 256 f
#define SM_MASK    151040                    // 256 f
#define SM_CO      152064                    // 64 float2
#define SM_RED     152576                    // 8 f
#define SM_RED2    152608                    // 8 f
#define SM_SCRATCH 152640                    // 512 f
#define SMEM_BYTES 154688

typedef unsigned long long u64;

// Precomputed globals
__device__ __nv_bfloat16 g_Bh[DD * 72];   // (W1+W2) hi, [k][c] padded to 72
__device__ __nv_bfloat16 g_Bl[DD * 72];   // lo
__device__ float g_Wb[DD * HH];           // W3 - W2
__device__ float g_c[BB * HH];            // tgt @ Wb + W_bias

__device__ __forceinline__ uint32_t smem_u32(const void* p) {
    return (uint32_t)__cvta_generic_to_shared(p);
}
__device__ __forceinline__ void cpa16(void* s, const void* g) {
    asm volatile("cp.async.cg.shared.global [%0], [%1], 16;" :: "r"(smem_u32(s)), "l"(g));
}
#define CP_COMMIT() asm volatile("cp.async.commit_group;")
#define CP_WAIT0()  asm volatile("cp.async.wait_group 0;")

__device__ __forceinline__ void ldsm4(uint32_t* r, uint32_t addr) {
    asm volatile("ldmatrix.sync.aligned.m8n8.x4.shared.b16 {%0,%1,%2,%3}, [%4];"
                 : "=r"(r[0]), "=r"(r[1]), "=r"(r[2]), "=r"(r[3]) : "r"(addr));
}
__device__ __forceinline__ void ldsm4t(uint32_t* r, uint32_t addr) {
    asm volatile("ldmatrix.sync.aligned.m8n8.x4.trans.shared.b16 {%0,%1,%2,%3}, [%4];"
                 : "=r"(r[0]), "=r"(r[1]), "=r"(r[2]), "=r"(r[3]) : "r"(addr));
}
__device__ __forceinline__ void mma16816(float* c, const uint32_t* a,
                                         uint32_t b0, uint32_t b1) {
    asm volatile(
        "mma.sync.aligned.m16n8k16.row.col.f32.bf16.bf16.f32 "
        "{%0,%1,%2,%3}, {%4,%5,%6,%7}, {%8,%9}, {%0,%1,%2,%3};"
        : "+f"(c[0]), "+f"(c[1]), "+f"(c[2]), "+f"(c[3])
        : "r"(a[0]), "r"(a[1]), "r"(a[2]), "r"(a[3]), "r"(b0), "r"(b1));
}

__global__ void fold_w_kernel(const float* __restrict__ W) {
    int idx = blockIdx.x * blockDim.x + threadIdx.x;   // DD*HH
    if (idx < DD * HH) {
        int k = idx >> 6, c = idx & 63;
        float w1 = W[k * HH + c];
        float w2 = W[(DD + k) * HH + c];
        float w3 = W[(2 * DD + k) * HH + c];
        float wa = w1 + w2;
        g_Wb[k * HH + c] = w3 - w2;
        __nv_bfloat16 hi = __float2bfloat16_rn(wa);
        __nv_bfloat16 lo = __float2bfloat16_rn(wa - __bfloat162float(hi));
        g_Bh[k * 72 + c] = hi;
        g_Bl[k * 72 + c] = lo;
    }
}

__global__ void cvec_kernel(const float* __restrict__ target,
                            const float* __restrict__ W_bias) {
    __shared__ float tgt[DD];
    int b = blockIdx.x;
    for (int i = threadIdx.x; i < DD; i += blockDim.x)
        tgt[i] = target[(size_t)b * DD + i];
    __syncthreads();
    int h = threadIdx.x;
    if (h < HH) {
        float acc = 0.f;
#pragma unroll 8
        for (int d = 0; d < DD; d++)
            acc = fmaf(tgt[d], g_Wb[d * HH + h], acc);
        g_c[b * HH + h] = acc + W_bias[h];
    }
}

__global__ __launch_bounds__(NT, 1)
void ta_main_kernel(const float* __restrict__ his,
                    const float* __restrict__ mask,
                    const float* __restrict__ O,
                    const float* __restrict__ O_bias,
                    float* __restrict__ out) {
    extern __shared__ __align__(16) char sm[];
    float*  alpha  = (float*)(sm + SM_ALPHA);
    float*  mask_s = (float*)(sm + SM_MASK);
    float2* cO_s   = (float2*)(sm + SM_CO);
    float*  red    = (float*)(sm + SM_RED);
    float*  red2   = (float*)(sm + SM_RED2);
    float*  scr    = (float*)(sm + SM_SCRATCH);

    const int b = blockIdx.x;
    const int tid = threadIdx.x;
    const int wid = tid >> 5;
    const int lane = tid & 31;
    const uint32_t smem_base = smem_u32(sm);

    // ---- Phase 0: loads ----
    // B weight images (hi+lo, each 18432 B) via cp.async
    for (int i = tid; i < 18432 / 16; i += NT) {
        cpa16(sm + B_HI_OFF + i * 16, (const char*)g_Bh + i * 16);
        cpa16(sm + B_LO_OFF + i * 16, (const char*)g_Bl + i * 16);
    }
    CP_COMMIT();

    if (tid < SS) mask_s[tid] = mask[(size_t)b * SS + tid];
    if (tid < HH) cO_s[tid] = make_float2(g_c[b * HH + tid], O[tid]);
    const float ob = O_bias[0];

    // zero-pad A rows 200..207 (both hi and lo)
    for (int i = tid; i < 2 * 272; i += NT) {     // 272 u64 per array
        int arr = (i < 272) ? A_HI_OFF : A_LO_OFF;
        int j = (i < 272) ? i : i - 272;
        *(u64*)(sm + arr + 200 * ASTRIDE + j * 8) = 0ull;
    }

    // his load + fp32->bf16 hi/lo split + STS (row-major, ASTRIDE)
    {
        const int k0 = 4 * lane;
        const float* hb = his + ((size_t)b * SS + (size_t)wid * ROWS_PER_WARP) * DD + k0;
#pragma unroll 5
        for (int i = 0; i < ROWS_PER_WARP; i++) {
            int s = wid * ROWS_PER_WARP + i;
            float4 v = *(const float4*)(hb + (size_t)i * DD);
            __nv_bfloat16 h0 = __float2bfloat16_rn(v.x);
            __nv_bfloat16 h1 = __float2bfloat16_rn(v.y);
            __nv_bfloat16 h2 = __float2bfloat16_rn(v.z);
            __nv_bfloat16 h3 = __float2bfloat16_rn(v.w);
            __nv_bfloat16 l0 = __float2bfloat16_rn(v.x - __bfloat162float(h0));
            __nv_bfloat16 l1 = __float2bfloat16_rn(v.y - __bfloat162float(h1));
            __nv_bfloat16 l2 = __float2bfloat16_rn(v.z - __bfloat162float(h2));
            __nv_bfloat16 l3 = __float2bfloat16_rn(v.w - __bfloat162float(h3));
            __nv_bfloat162 ph01 = {h0, h1}, ph23 = {h2, h3};
            __nv_bfloat162 pl01 = {l0, l1}, pl23 = {l2, l3};
            u64 hp = ((u64)*(uint32_t*)&ph23 << 32) | *(uint32_t*)&ph01;
            u64 lp = ((u64)*(uint32_t*)&pl23 << 32) | *(uint32_t*)&pl01;
            int off = s * ASTRIDE + k0 * 2;
            *(u64*)(sm + A_HI_OFF + off) = hp;
            *(u64*)(sm + A_LO_OFF + off) = lp;
        }
    }

    CP_WAIT0();
    __syncthreads();

    // ---- Phase 1: GEMM via mma.sync bf16 3-split -> alpha ----
    {
        const int g = lane >> 3;            // ldmatrix quad group
        const int r = lane & 7;
        const int arow_l = r + (g & 1) * 8;            // row within 16-strip
        const int acol_l = (g >> 1) * 16;              // +16B for k high half
        const int brow_l = r + (g & 1) * 8;            // row within k16 tile
        const uint32_t aH = smem_base + A_HI_OFF;
        const uint32_t aL = smem_base + A_LO_OFF;
        const uint32_t bH = smem_base + B_HI_OFF;
        const uint32_t bL = smem_base + B_LO_OFF;

        for (int strip = wid; strip < NSTRIP; strip += NW) {
            float c[8][4];
#pragma unroll
            for (int nt = 0; nt < 8; nt++)
#pragma unroll
                for (int q = 0; q < 4; q++) c[nt][q] = 0.f;

#pragma unroll 1
            for (int sp = 0; sp < 3; sp++) {
                const uint32_t Ab = (sp == 2 ? aL : aH)
                                  + (strip * 16 + arow_l) * ASTRIDE + acol_l;
                const uint32_t Bb = (sp == 1 ? bL : bH)
                                  + brow_l * BSTRIDE + (g >> 1) * 16;
#pragma unroll
                for (int kk = 0; kk < 8; kk++) {
                    uint32_t a[4];
                    ldsm4(a, Ab + kk * 32);
#pragma unroll
                    for (int np2 = 0; np2 < 4; np2++) {
                        uint32_t bf[4];
                        ldsm4t(bf, Bb + kk * 16 * BSTRIDE + np2 * 32);
                        mma16816(c[2 * np2],     a, bf[0], bf[1]);
                        mma16816(c[2 * np2 + 1], a, bf[2], bf[3]);
                    }
                }
            }

            // epilogue: relu(C + cvec) dot O, reduce over quad -> alpha rows
            float v0 = 0.f, v1 = 0.f;
            const int cbase = 2 * (lane & 3);
#pragma unroll
            for (int nt = 0; nt < 8; nt++) {
                int col0 = nt * 8 + cbase;
                float2 co0 = cO_s[col0];
                float2 co1 = cO_s[col0 + 1];
                v0 = fmaf(fmaxf(c[nt][0] + co0.x, 0.f), co0.y, v0);
                v0 = fmaf(fmaxf(c[nt][1] + co1.x, 0.f), co1.y, v0);
                v1 = fmaf(fmaxf(c[nt][2] + co0.x, 0.f), co0.y, v1);
                v1 = fmaf(fmaxf(c[nt][3] + co1.x, 0.f), co1.y, v1);
            }
            v0 += __shfl_xor_sync(0xffffffffu, v0, 1);
            v0 += __shfl_xor_sync(0xffffffffu, v0, 2);
            v1 += __shfl_xor_sync(0xffffffffu, v1, 1);
            v1 += __shfl_xor_sync(0xffffffffu, v1, 2);
            if ((lane & 3) == 0) {
                int s0 = strip * 16 + (lane >> 2);
                if (s0 < SS)     alpha[s0]     = v0 + ob - mask_s[s0] * MASK_SCALE;
                if (s0 + 8 < SS) alpha[s0 + 8] = v1 + ob - mask_s[s0 + 8] * MASK_SCALE;
            }
        }
    }
    __syncthreads();

    // ---- Phase 2: softmax over alpha[0..SS) ----
    {
        float vv = (tid < SS) ? alpha[tid] : -INFINITY;
        float m = vv;
#pragma unroll
        for (int off = 16; off > 0; off >>= 1)
            m = fmaxf(m, __shfl_xor_sync(0xffffffffu, m, off));
        if (lane == 0) red[wid] = m;
        __syncthreads();
        m = red[0];
#pragma unroll
        for (int w = 1; w < NW; w++) m = fmaxf(m, red[w]);

        float e = (tid < SS) ? __expf(vv - m) : 0.f;
        float ssum = e;
#pragma unroll
        for (int off = 16; off > 0; off >>= 1)
            ssum += __shfl_xor_sync(0xffffffffu, ssum, off);
        if (lane == 0) red2[wid] = ssum;
        __syncthreads();
        float tot = 0.f;
#pragma unroll
        for (int w = 0; w < NW; w++) tot += red2[w];

        if (tid < SS) alpha[tid] = e / tot;
    }
    __syncthreads();

    // ---- Phase 3: pooling out[b,d] = sum_s attn[s] * (Ahi+Alo)[s,d] ----
    {
        const int p = tid & 63;          // d-pair: d = 2p, 2p+1
        const int q = tid >> 6;          // s quarter (50 rows)
        float ax = 0.f, ay = 0.f;
        const int sbeg = q * 50;
#pragma unroll 5
        for (int i = 0; i < 50; i++) {
            int s = sbeg + i;
            int off = s * ASTRIDE + p * 4;
            __nv_bfloat162 h2 = *(__nv_bfloat162*)(sm + A_HI_OFF + off);
            __nv_bfloat162 l2 = *(__nv_bfloat162*)(sm + A_LO_OFF + off);
            float2 fh = __bfloat1622float2(h2);
            float2 fl = __bfloat1622float2(l2);
            float a = alpha[s];
            ax = fmaf(a, fh.x + fl.x, ax);
            ay = fmaf(a, fh.y + fl.y, ay);
        }
        scr[q * 128 + 2 * p]     = ax;
        scr[q * 128 + 2 * p + 1] = ay;
        __syncthreads();
        if (tid < DD) {
            float r2 = scr[tid] + scr[128 + tid] + scr[256 + tid] + scr[384 + tid];
            out[(size_t)b * DD + tid] = r2;
        }
    }
}

extern "C" void kernel_launch(void* const* d_in, const int* in_sizes, int n_in,
                              void* d_out, int out_size) {
    const float* his    = (const float*)d_in[0];
    const float* target = (const float*)d_in[1];
    const float* mask   = (const float*)d_in[2];
    const float* W      = (const float*)d_in[3];
    const float* W_bias = (const float*)d_in[4];
    const float* O      = (const float*)d_in[5];
    const float* O_bias = (const float*)d_in[6];
    float* out = (float*)d_out;

    cudaFuncSetAttribute(ta_main_kernel,
                         cudaFuncAttributeMaxDynamicSharedMemorySize, SMEM_BYTES);

    fold_w_kernel<<<(DD * HH + 255) / 256, 256>>>(W);
    cvec_kernel<<<BB, 128>>>(target, W_bias);
    ta_main_kernel<<<BB, NT, SMEM_BYTES>>>(his, mask, O, O_bias, out);
}

// round 5
// speedup vs baseline: 3.7093x; 1.7441x over previous
#include <cuda_runtime.h>
#include <cuda_fp16.h>
#include <math.h>
#include <stdint.h>

#define BB 2048
#define SS 200
#define DD 128
#define HH 64
#define MASK_SCALE 1e10f
#define NT 256
#define NW (NT / 32)
#define ROWS_PER_WARP (SS / NW)      // 25
#define NSTRIP 13                    // ceil(200/16), rows 200..207 zero-padded

#define ASTRIDE 272                  // bytes per A row (136 fp16) = 17*16
#define BSTRIDE 144                  // bytes per B row (72 fp16)  = 9*16

// ---- smem byte layout ----
#define A_OFF      0                         // 208*272 = 56576
#define B_HI_OFF   56576                     // 128*144 = 18432
#define B_LO_OFF   75008                     // 18432
#define SM_ALPHA   93440                     // 256 f
#define SM_MASK    94464                     // 256 f
#define SM_CO      95488                     // 64 float2
#define SM_RED     96000                     // 8 f
#define SM_RED2    96032                     // 8 f
#define SM_SCRATCH 96064                     // 512 f
#define SMEM_BYTES 98112                     // ~95.8 KB -> 2 CTAs/SM

typedef unsigned long long u64;

// Precomputed globals
__device__ __half g_Bh[DD * 72];   // (W1+W2) hi fp16, [k][c] padded to 72
__device__ __half g_Bl[DD * 72];   // lo
__device__ float g_Wb[DD * HH];    // W3 - W2
__device__ float g_c[BB * HH];     // tgt @ Wb + W_bias

__device__ __forceinline__ uint32_t smem_u32(const void* p) {
    return (uint32_t)__cvta_generic_to_shared(p);
}
__device__ __forceinline__ void cpa16(void* s, const void* g) {
    asm volatile("cp.async.cg.shared.global [%0], [%1], 16;" :: "r"(smem_u32(s)), "l"(g));
}
#define CP_COMMIT() asm volatile("cp.async.commit_group;")
#define CP_WAIT0()  asm volatile("cp.async.wait_group 0;")

__device__ __forceinline__ void ldsm4(uint32_t* r, uint32_t addr) {
    asm volatile("ldmatrix.sync.aligned.m8n8.x4.shared.b16 {%0,%1,%2,%3}, [%4];"
                 : "=r"(r[0]), "=r"(r[1]), "=r"(r[2]), "=r"(r[3]) : "r"(addr));
}
__device__ __forceinline__ void ldsm4t(uint32_t* r, uint32_t addr) {
    asm volatile("ldmatrix.sync.aligned.m8n8.x4.trans.shared.b16 {%0,%1,%2,%3}, [%4];"
                 : "=r"(r[0]), "=r"(r[1]), "=r"(r[2]), "=r"(r[3]) : "r"(addr));
}
__device__ __forceinline__ void mma16816(float* c, const uint32_t* a,
                                         uint32_t b0, uint32_t b1) {
    asm volatile(
        "mma.sync.aligned.m16n8k16.row.col.f32.f16.f16.f32 "
        "{%0,%1,%2,%3}, {%4,%5,%6,%7}, {%8,%9}, {%0,%1,%2,%3};"
        : "+f"(c[0]), "+f"(c[1]), "+f"(c[2]), "+f"(c[3])
        : "r"(a[0]), "r"(a[1]), "r"(a[2]), "r"(a[3]), "r"(b0), "r"(b1));
}

__global__ void fold_w_kernel(const float* __restrict__ W) {
    int idx = blockIdx.x * blockDim.x + threadIdx.x;   // DD*HH
    if (idx < DD * HH) {
        int k = idx >> 6, c = idx & 63;
        float w1 = W[k * HH + c];
        float w2 = W[(DD + k) * HH + c];
        float w3 = W[(2 * DD + k) * HH + c];
        float wa = w1 + w2;
        g_Wb[k * HH + c] = w3 - w2;
        __half hi = __float2half_rn(wa);
        __half lo = __float2half_rn(wa - __half2float(hi));
        g_Bh[k * 72 + c] = hi;
        g_Bl[k * 72 + c] = lo;
    }
}

__global__ void cvec_kernel(const float* __restrict__ target,
                            const float* __restrict__ W_bias) {
    __shared__ float tgt[DD];
    int b = blockIdx.x;
    for (int i = threadIdx.x; i < DD; i += blockDim.x)
        tgt[i] = target[(size_t)b * DD + i];
    __syncthreads();
    int h = threadIdx.x;
    if (h < HH) {
        float acc = 0.f;
#pragma unroll 8
        for (int d = 0; d < DD; d++)
            acc = fmaf(tgt[d], g_Wb[d * HH + h], acc);
        g_c[b * HH + h] = acc + W_bias[h];
    }
}

__global__ __launch_bounds__(NT, 2)
void ta_main_kernel(const float* __restrict__ his,
                    const float* __restrict__ mask,
                    const float* __restrict__ O,
                    const float* __restrict__ O_bias,
                    float* __restrict__ out) {
    extern __shared__ __align__(16) char sm[];
    float*  alpha  = (float*)(sm + SM_ALPHA);
    float*  mask_s = (float*)(sm + SM_MASK);
    float2* cO_s   = (float2*)(sm + SM_CO);
    float*  red    = (float*)(sm + SM_RED);
    float*  red2   = (float*)(sm + SM_RED2);
    float*  scr    = (float*)(sm + SM_SCRATCH);

    const int b = blockIdx.x;
    const int tid = threadIdx.x;
    const int wid = tid >> 5;
    const int lane = tid & 31;
    const uint32_t smem_base = smem_u32(sm);

    // ---- Phase 0: loads ----
    // B weight images (hi+lo, each 18432 B) via cp.async
    for (int i = tid; i < 18432 / 16; i += NT) {
        cpa16(sm + B_HI_OFF + i * 16, (const char*)g_Bh + i * 16);
        cpa16(sm + B_LO_OFF + i * 16, (const char*)g_Bl + i * 16);
    }
    CP_COMMIT();

    if (tid < SS) mask_s[tid] = mask[(size_t)b * SS + tid];
    if (tid < HH) cO_s[tid] = make_float2(g_c[b * HH + tid], O[tid]);
    const float ob = O_bias[0];

    // zero-pad A rows 200..207 (272 u64)
    for (int i = tid; i < 272; i += NT)
        *(u64*)(sm + A_OFF + 200 * ASTRIDE + i * 8) = 0ull;

    // his load + fp32->fp16 + STS (row-major, ASTRIDE)
    {
        const int k0 = 4 * lane;
        const float* hb = his + ((size_t)b * SS + (size_t)wid * ROWS_PER_WARP) * DD + k0;
#pragma unroll 5
        for (int i = 0; i < ROWS_PER_WARP; i++) {
            int s = wid * ROWS_PER_WARP + i;
            float4 v = *(const float4*)(hb + (size_t)i * DD);
            __half2 p01 = __floats2half2_rn(v.x, v.y);
            __half2 p23 = __floats2half2_rn(v.z, v.w);
            u64 hp = ((u64)*(uint32_t*)&p23 << 32) | *(uint32_t*)&p01;
            *(u64*)(sm + A_OFF + s * ASTRIDE + k0 * 2) = hp;
        }
    }

    CP_WAIT0();
    __syncthreads();

    // ---- Phase 1: GEMM via mma.sync fp16, products Ah@Bh + Ah@Bl ----
    {
        const int g = lane >> 3;            // ldmatrix quad group
        const int r = lane & 7;
        const int arow_l = r + (g & 1) * 8;            // row within 16-strip
        const int acol_l = (g >> 1) * 16;              // +16B for k high half
        const int brow_l = r + (g & 1) * 8;            // row within k16 tile
        const uint32_t aB = smem_base + A_OFF;
        const uint32_t bH = smem_base + B_HI_OFF + brow_l * BSTRIDE + (g >> 1) * 16;
        const uint32_t bL = smem_base + B_LO_OFF + brow_l * BSTRIDE + (g >> 1) * 16;

        for (int strip = wid; strip < NSTRIP; strip += NW) {
            float c[8][4];
#pragma unroll
            for (int nt = 0; nt < 8; nt++)
#pragma unroll
                for (int q = 0; q < 4; q++) c[nt][q] = 0.f;

            const uint32_t Ab = aB + (strip * 16 + arow_l) * ASTRIDE + acol_l;
#pragma unroll
            for (int kk = 0; kk < 8; kk++) {
                uint32_t a[4];
                ldsm4(a, Ab + kk * 32);
                const uint32_t koff = kk * 16 * BSTRIDE;
#pragma unroll
                for (int np2 = 0; np2 < 4; np2++) {
                    uint32_t bf[4];
                    ldsm4t(bf, bH + koff + np2 * 32);
                    mma16816(c[2 * np2],     a, bf[0], bf[1]);
                    mma16816(c[2 * np2 + 1], a, bf[2], bf[3]);
                    uint32_t bl[4];
                    ldsm4t(bl, bL + koff + np2 * 32);
                    mma16816(c[2 * np2],     a, bl[0], bl[1]);
                    mma16816(c[2 * np2 + 1], a, bl[2], bl[3]);
                }
            }

            // epilogue: relu(C + cvec) dot O, quad reduce -> alpha rows
            float v0 = 0.f, v1 = 0.f;
            const int cbase = 2 * (lane & 3);
#pragma unroll
            for (int nt = 0; nt < 8; nt++) {
                int col0 = nt * 8 + cbase;
                float2 co0 = cO_s[col0];
                float2 co1 = cO_s[col0 + 1];
                v0 = fmaf(fmaxf(c[nt][0] + co0.x, 0.f), co0.y, v0);
                v0 = fmaf(fmaxf(c[nt][1] + co1.x, 0.f), co1.y, v0);
                v1 = fmaf(fmaxf(c[nt][2] + co0.x, 0.f), co0.y, v1);
                v1 = fmaf(fmaxf(c[nt][3] + co1.x, 0.f), co1.y, v1);
            }
            v0 += __shfl_xor_sync(0xffffffffu, v0, 1);
            v0 += __shfl_xor_sync(0xffffffffu, v0, 2);
            v1 += __shfl_xor_sync(0xffffffffu, v1, 1);
            v1 += __shfl_xor_sync(0xffffffffu, v1, 2);
            if ((lane & 3) == 0) {
                int s0 = strip * 16 + (lane >> 2);
                if (s0 < SS)     alpha[s0]     = v0 + ob - mask_s[s0] * MASK_SCALE;
                if (s0 + 8 < SS) alpha[s0 + 8] = v1 + ob - mask_s[s0 + 8] * MASK_SCALE;
            }
        }
    }
    __syncthreads();

    // ---- Phase 2: softmax over alpha[0..SS) ----
    {
        float vv = (tid < SS) ? alpha[tid] : -INFINITY;
        float m = vv;
#pragma unroll
        for (int off = 16; off > 0; off >>= 1)
            m = fmaxf(m, __shfl_xor_sync(0xffffffffu, m, off));
        if (lane == 0) red[wid] = m;
        __syncthreads();
        m = red[0];
#pragma unroll
        for (int w = 1; w < NW; w++) m = fmaxf(m, red[w]);

        float e = (tid < SS) ? __expf(vv - m) : 0.f;
        float ssum = e;
#pragma unroll
        for (int off = 16; off > 0; off >>= 1)
            ssum += __shfl_xor_sync(0xffffffffu, ssum, off);
        if (lane == 0) red2[wid] = ssum;
        __syncthreads();
        float tot = 0.f;
#pragma unroll
        for (int w = 0; w < NW; w++) tot += red2[w];

        if (tid < SS) alpha[tid] = e / tot;
    }
    __syncthreads();

    // ---- Phase 3: pooling out[b,d] = sum_s attn[s] * A[s,d] ----
    {
        const int p = tid & 63;          // d-pair: d = 2p, 2p+1
        const int q = tid >> 6;          // s quarter (50 rows)
        float ax = 0.f, ay = 0.f;
        const int sbeg = q * 50;
#pragma unroll 5
        for (int i = 0; i < 50; i++) {
            int s = sbeg + i;
            __half2 h2 = *(__half2*)(sm + A_OFF + s * ASTRIDE + p * 4);
            float2 fh = __half22float2(h2);
            float a = alpha[s];
            ax = fmaf(a, fh.x, ax);
            ay = fmaf(a, fh.y, ay);
        }
        scr[q * 128 + 2 * p]     = ax;
        scr[q * 128 + 2 * p + 1] = ay;
        __syncthreads();
        if (tid < DD) {
            float r2 = scr[tid] + scr[128 + tid] + scr[256 + tid] + scr[384 + tid];
            out[(size_t)b * DD + tid] = r2;
        }
    }
}

extern "C" void kernel_launch(void* const* d_in, const int* in_sizes, int n_in,
                              void* d_out, int out_size) {
    const float* his    = (const float*)d_in[0];
    const float* target = (const float*)d_in[1];
    const float* mask   = (const float*)d_in[2];
    const float* W      = (const float*)d_in[3];
    const float* W_bias = (const float*)d_in[4];
    const float* O      = (const float*)d_in[5];
    const float* O_bias = (const float*)d_in[6];
    float* out = (float*)d_out;

    cudaFuncSetAttribute(ta_main_kernel,
                         cudaFuncAttributeMaxDynamicSharedMemorySize, SMEM_BYTES);

    fold_w_kernel<<<(DD * HH + 255) / 256, 256>>>(W);
    cvec_kernel<<<BB, 128>>>(target, W_bias);
    ta_main_kernel<<<BB, NT, SMEM_BYTES>>>(his, mask, O, O_bias, out);
}

// round 6
// speedup vs baseline: 4.3844x; 1.1820x over previous
#include <cuda_runtime.h>
#include <cuda_fp16.h>
#include <math.h>
#include <stdint.h>

#define BB 2048
#define SS 200
#define DD 128
#define HH 64
#define MASK_SCALE 1e10f
#define NT 256
#define NW (NT / 32)
#define ROWS_PER_WARP (SS / NW)      // 25
#define NSTRIP 13                    // ceil(200/16), rows 200..207 zero-padded

#define ASTRIDE 272                  // bytes per A row (136 fp16) = 17*16
#define BSTRIDE 144                  // bytes per B row (72 fp16)  = 9*16

// ---- smem byte layout ----
#define A_OFF      0                         // 208*272 = 56576
#define B_OFF      56576                     // 128*144 = 18432
#define SM_ALPHA   75008                     // 256 f
#define SM_MASK    76032                     // 256 f
#define SM_CO      77056                     // 64 float2
#define SM_RED     77568                     // 8 f
#define SM_RED2    77600                     // 8 f
#define SM_SCRATCH 77632                     // 512 f
#define SMEM_BYTES 79680                     // ~77.8 KB -> 2 CTAs/SM

typedef unsigned long long u64;

// Precomputed globals
__device__ __half g_Bh[DD * 72];   // (W1+W2) fp16, [k][c] padded to 72
__device__ float g_Wb[DD * HH];    // W3 - W2
__device__ float g_c[BB * HH];     // tgt @ Wb + W_bias

__device__ __forceinline__ uint32_t smem_u32(const void* p) {
    return (uint32_t)__cvta_generic_to_shared(p);
}
__device__ __forceinline__ void cpa16(void* s, const void* g) {
    asm volatile("cp.async.cg.shared.global [%0], [%1], 16;" :: "r"(smem_u32(s)), "l"(g));
}
#define CP_COMMIT() asm volatile("cp.async.commit_group;")
#define CP_WAIT0()  asm volatile("cp.async.wait_group 0;")

__device__ __forceinline__ void ldsm4(uint32_t* r, uint32_t addr) {
    asm volatile("ldmatrix.sync.aligned.m8n8.x4.shared.b16 {%0,%1,%2,%3}, [%4];"
                 : "=r"(r[0]), "=r"(r[1]), "=r"(r[2]), "=r"(r[3]) : "r"(addr));
}
__device__ __forceinline__ void ldsm4t(uint32_t* r, uint32_t addr) {
    asm volatile("ldmatrix.sync.aligned.m8n8.x4.trans.shared.b16 {%0,%1,%2,%3}, [%4];"
                 : "=r"(r[0]), "=r"(r[1]), "=r"(r[2]), "=r"(r[3]) : "r"(addr));
}
__device__ __forceinline__ void mma16816(float* c, const uint32_t* a,
                                         uint32_t b0, uint32_t b1) {
    asm volatile(
        "mma.sync.aligned.m16n8k16.row.col.f32.f16.f16.f32 "
        "{%0,%1,%2,%3}, {%4,%5,%6,%7}, {%8,%9}, {%0,%1,%2,%3};"
        : "+f"(c[0]), "+f"(c[1]), "+f"(c[2]), "+f"(c[3])
        : "r"(a[0]), "r"(a[1]), "r"(a[2]), "r"(a[3]), "r"(b0), "r"(b1));
}

__global__ void fold_w_kernel(const float* __restrict__ W) {
    int idx = blockIdx.x * blockDim.x + threadIdx.x;   // DD*HH
    if (idx < DD * HH) {
        int k = idx >> 6, c = idx & 63;
        float w1 = W[k * HH + c];
        float w2 = W[(DD + k) * HH + c];
        float w3 = W[(2 * DD + k) * HH + c];
        float wa = w1 + w2;
        g_Wb[k * HH + c] = w3 - w2;
        g_Bh[k * 72 + c] = __float2half_rn(wa);
    }
}

__global__ void cvec_kernel(const float* __restrict__ target,
                            const float* __restrict__ W_bias) {
    __shared__ float tgt[DD];
    int b = blockIdx.x;
    for (int i = threadIdx.x; i < DD; i += blockDim.x)
        tgt[i] = target[(size_t)b * DD + i];
    __syncthreads();
    int h = threadIdx.x;
    if (h < HH) {
        float acc = 0.f;
#pragma unroll 8
        for (int d = 0; d < DD; d++)
            acc = fmaf(tgt[d], g_Wb[d * HH + h], acc);
        g_c[b * HH + h] = acc + W_bias[h];
    }
}

__global__ __launch_bounds__(NT, 2)
void ta_main_kernel(const float* __restrict__ his,
                    const float* __restrict__ mask,
                    const float* __restrict__ O,
                    const float* __restrict__ O_bias,
                    float* __restrict__ out) {
    extern __shared__ __align__(16) char sm[];
    float*  alpha  = (float*)(sm + SM_ALPHA);
    float*  mask_s = (float*)(sm + SM_MASK);
    float2* cO_s   = (float2*)(sm + SM_CO);
    float*  red    = (float*)(sm + SM_RED);
    float*  red2   = (float*)(sm + SM_RED2);
    float*  scr    = (float*)(sm + SM_SCRATCH);

    const int b = blockIdx.x;
    const int tid = threadIdx.x;
    const int wid = tid >> 5;
    const int lane = tid & 31;
    const uint32_t smem_base = smem_u32(sm);

    // ---- Phase 0: loads ----
    // B weight image (18432 B) via cp.async
    for (int i = tid; i < 18432 / 16; i += NT)
        cpa16(sm + B_OFF + i * 16, (const char*)g_Bh + i * 16);
    CP_COMMIT();

    if (tid < SS) mask_s[tid] = mask[(size_t)b * SS + tid];
    if (tid < HH) cO_s[tid] = make_float2(g_c[b * HH + tid], O[tid]);
    const float ob = O_bias[0];

    // zero-pad A rows 200..207 (272 u64)
    for (int i = tid; i < 272; i += NT)
        *(u64*)(sm + A_OFF + 200 * ASTRIDE + i * 8) = 0ull;

    // his load + fp32->fp16 + STS (row-major, ASTRIDE)
    {
        const int k0 = 4 * lane;
        const float* hb = his + ((size_t)b * SS + (size_t)wid * ROWS_PER_WARP) * DD + k0;
#pragma unroll 5
        for (int i = 0; i < ROWS_PER_WARP; i++) {
            int s = wid * ROWS_PER_WARP + i;
            float4 v = *(const float4*)(hb + (size_t)i * DD);
            __half2 p01 = __floats2half2_rn(v.x, v.y);
            __half2 p23 = __floats2half2_rn(v.z, v.w);
            u64 hp = ((u64)*(uint32_t*)&p23 << 32) | *(uint32_t*)&p01;
            *(u64*)(sm + A_OFF + s * ASTRIDE + k0 * 2) = hp;
        }
    }

    CP_WAIT0();
    __syncthreads();

    // ---- Phase 1: GEMM via mma.sync fp16, single product, B-frag reuse ----
    {
        const int g = lane >> 3;            // ldmatrix quad group
        const int r = lane & 7;
        const int arow_l = r + (g & 1) * 8;            // row within 16-strip
        const int acol_l = (g >> 1) * 16;              // +16B for k high half
        const int brow_l = r + (g & 1) * 8;            // row within k16 tile
        const uint32_t aB = smem_base + A_OFF;
        const uint32_t bH = smem_base + B_OFF + brow_l * BSTRIDE + (g >> 1) * 16;

        const int strip0 = wid;             // 0..7
        const int strip1 = wid + 8;         // 8..15; valid when < NSTRIP
        const bool two = (strip1 < NSTRIP);

        float c0[8][4], c1[8][4];
#pragma unroll
        for (int nt = 0; nt < 8; nt++)
#pragma unroll
            for (int q = 0; q < 4; q++) { c0[nt][q] = 0.f; c1[nt][q] = 0.f; }

        const uint32_t Ab0 = aB + (strip0 * 16 + arow_l) * ASTRIDE + acol_l;
        const uint32_t Ab1 = aB + (strip1 * 16 + arow_l) * ASTRIDE + acol_l;

#pragma unroll
        for (int kk = 0; kk < 8; kk++) {
            uint32_t a0[4], a1[4];
            ldsm4(a0, Ab0 + kk * 32);
            if (two) ldsm4(a1, Ab1 + kk * 32);
            const uint32_t koff = kk * 16 * BSTRIDE;
#pragma unroll
            for (int np2 = 0; np2 < 4; np2++) {
                uint32_t bf[4];
                ldsm4t(bf, bH + koff + np2 * 32);
                mma16816(c0[2 * np2],     a0, bf[0], bf[1]);
                mma16816(c0[2 * np2 + 1], a0, bf[2], bf[3]);
                if (two) {
                    mma16816(c1[2 * np2],     a1, bf[0], bf[1]);
                    mma16816(c1[2 * np2 + 1], a1, bf[2], bf[3]);
                }
            }
        }

        // epilogue: relu(C + cvec) dot O, quad reduce -> alpha rows
        const int cbase = 2 * (lane & 3);
#pragma unroll
        for (int pass = 0; pass < 2; pass++) {
            if (pass == 1 && !two) break;
            float (*c)[4] = pass ? c1 : c0;
            const int strip = pass ? strip1 : strip0;
            float v0 = 0.f, v1 = 0.f;
#pragma unroll
            for (int nt = 0; nt < 8; nt++) {
                int col0 = nt * 8 + cbase;
                float2 co0 = cO_s[col0];
                float2 co1 = cO_s[col0 + 1];
                v0 = fmaf(fmaxf(c[nt][0] + co0.x, 0.f), co0.y, v0);
                v0 = fmaf(fmaxf(c[nt][1] + co1.x, 0.f), co1.y, v0);
                v1 = fmaf(fmaxf(c[nt][2] + co0.x, 0.f), co0.y, v1);
                v1 = fmaf(fmaxf(c[nt][3] + co1.x, 0.f), co1.y, v1);
            }
            v0 += __shfl_xor_sync(0xffffffffu, v0, 1);
            v0 += __shfl_xor_sync(0xffffffffu, v0, 2);
            v1 += __shfl_xor_sync(0xffffffffu, v1, 1);
            v1 += __shfl_xor_sync(0xffffffffu, v1, 2);
            if ((lane & 3) == 0) {
                int s0 = strip * 16 + (lane >> 2);
                if (s0 < SS)     alpha[s0]     = v0 + ob - mask_s[s0] * MASK_SCALE;
                if (s0 + 8 < SS) alpha[s0 + 8] = v1 + ob - mask_s[s0 + 8] * MASK_SCALE;
            }
        }
    }
    __syncthreads();

    // ---- Phase 2: softmax over alpha[0..SS) ----
    {
        float vv = (tid < SS) ? alpha[tid] : -INFINITY;
        float m = vv;
#pragma unroll
        for (int off = 16; off > 0; off >>= 1)
            m = fmaxf(m, __shfl_xor_sync(0xffffffffu, m, off));
        if (lane == 0) red[wid] = m;
        __syncthreads();
        m = red[0];
#pragma unroll
        for (int w = 1; w < NW; w++) m = fmaxf(m, red[w]);

        float e = (tid < SS) ? __expf(vv - m) : 0.f;
        float ssum = e;
#pragma unroll
        for (int off = 16; off > 0; off >>= 1)
            ssum += __shfl_xor_sync(0xffffffffu, ssum, off);
        if (lane == 0) red2[wid] = ssum;
        __syncthreads();
        float tot = 0.f;
#pragma unroll
        for (int w = 0; w < NW; w++) tot += red2[w];

        if (tid < SS) alpha[tid] = e / tot;
    }
    __syncthreads();

    // ---- Phase 3: pooling out[b,d] = sum_s attn[s] * A[s,d] ----
    {
        const int p = tid & 63;          // d-pair: d = 2p, 2p+1
        const int q = tid >> 6;          // s quarter (50 rows)
        float ax = 0.f, ay = 0.f;
        const int sbeg = q * 50;
#pragma unroll 5
        for (int i = 0; i < 50; i++) {
            int s = sbeg + i;
            __half2 h2 = *(__half2*)(sm + A_OFF + s * ASTRIDE + p * 4);
            float2 fh = __half22float2(h2);
            float a = alpha[s];
            ax = fmaf(a, fh.x, ax);
            ay = fmaf(a, fh.y, ay);
        }
        scr[q * 128 + 2 * p]     = ax;
        scr[q * 128 + 2 * p + 1] = ay;
        __syncthreads();
        if (tid < DD) {
            float r2 = scr[tid] + scr[128 + tid] + scr[256 + tid] + scr[384 + tid];
            out[(size_t)b * DD + tid] = r2;
        }
    }
}

extern "C" void kernel_launch(void* const* d_in, const int* in_sizes, int n_in,
                              void* d_out, int out_size) {
    const float* his    = (const float*)d_in[0];
    const float* target = (const float*)d_in[1];
    const float* mask   = (const float*)d_in[2];
    const float* W      = (const float*)d_in[3];
    const float* W_bias = (const float*)d_in[4];
    const float* O      = (const float*)d_in[5];
    const float* O_bias = (const float*)d_in[6];
    float* out = (float*)d_out;

    cudaFuncSetAttribute(ta_main_kernel,
                         cudaFuncAttributeMaxDynamicSharedMemorySize, SMEM_BYTES);

    fold_w_kernel<<<(DD * HH + 255) / 256, 256>>>(W);
    cvec_kernel<<<BB, 128>>>(target, W_bias);
    ta_main_kernel<<<BB, NT, SMEM_BYTES>>>(his, mask, O, O_bias, out);
}